// round 14
// baseline (speedup 1.0000x reference)
#include <cuda_runtime.h>
#include <cstddef>
#include <cstdint>

typedef unsigned long long u64;

// M matrix in DUAL-PORT split layout (2048 floats total):
//   floats [0, 1024):  SMEM half — rows 0..7  as row-pairs j2=0..3
//   floats [1024,2048): CONST half — rows 8..15 as row-pairs j2=4..7
__device__ float g_M[2048];
__constant__ ulonglong2 cM[256];   // 4 KB const half

// ---------------------------------------------------------------------------
// Precompute: simulate the weight-only circuit on all 32 basis states for
// each of the 4 generators. Thread t = g*32 + k simulates column k of U_g.
// ---------------------------------------------------------------------------
__global__ void precompute_M_kernel(const float* __restrict__ qp)
{
    int t = threadIdx.x;
    if (t >= 128) return;
    int g = t >> 5;
    int k = t & 31;

    float st[32];
#pragma unroll
    for (int i = 0; i < 32; ++i) st[i] = 0.0f;
    st[k] = 1.0f;

#pragma unroll 1
    for (int d = 0; d < 6; ++d) {
#pragma unroll
        for (int w = 0; w < 5; ++w) {
            float th = qp[g * 30 + d * 5 + w] * 0.5f;
            float s, c;
            __sincosf(th, &s, &c);
            const int stride = 16 >> w;
#pragma unroll
            for (int i = 0; i < 32; ++i) {
                if (i & stride) continue;
                float a0 = st[i];
                float a1 = st[i + stride];
                st[i]          = c * a0 - s * a1;
                st[i + stride] = s * a0 + c * a1;
            }
        }
#pragma unroll
        for (int w = 0; w < 4; ++w) {
            const int m = (16 >> w) | (8 >> w);
#pragma unroll
            for (int i = 0; i < 32; ++i)
                if ((i & m) == m) st[i] = -st[i];
        }
    }

#pragma unroll
    for (int j2 = 0; j2 < 4; ++j2) {
        g_M[((g * 32 + k) * 4 + j2) * 2 + 0] = st[2 * j2 + 0];
        g_M[((g * 32 + k) * 4 + j2) * 2 + 1] = st[2 * j2 + 1];
    }
#pragma unroll
    for (int j2 = 0; j2 < 4; ++j2) {
        g_M[1024 + ((g * 32 + k) * 4 + j2) * 2 + 0] = st[8 + 2 * j2 + 0];
        g_M[1024 + ((g * 32 + k) * 4 + j2) * 2 + 1] = st[8 + 2 * j2 + 1];
    }
}

// ---------------------------------------------------------------------------
// Packed f32x2 helpers (Blackwell sm_103a)
// ---------------------------------------------------------------------------
__device__ __forceinline__ u64 pk2(float lo, float hi) {
    u64 r;
    asm("mov.b64 %0, {%1, %2};" : "=l"(r) : "f"(lo), "f"(hi));
    return r;
}
__device__ __forceinline__ void upk2(u64 v, float& lo, float& hi) {
    asm("mov.b64 {%0, %1}, %2;" : "=f"(lo), "=f"(hi) : "l"(v));
}
__device__ __forceinline__ u64 fma2(u64 a, u64 b, u64 c) {
    u64 d;
    asm("fma.rn.f32x2 %0, %1, %2, %3;" : "=l"(d) : "l"(a), "l"(b), "l"(c));
    return d;
}
__device__ __forceinline__ u64 mul2(u64 a, u64 b) {
    u64 d;
    asm("mul.rn.f32x2 %0, %1, %2;" : "=l"(d) : "l"(a), "l"(b));
    return d;
}

// Scalar Kronecker factors for ONE batch element.
__device__ __forceinline__ void build_psi_scalar(
    float4 q, float pa[8], float pb[4])
{
    float a0 = q.x, a1 = q.y, a2 = q.z;
    float h0 = 0.5f   * a0;
    float h1 = 0.375f * a0 + 0.125f * a1;
    float h2 = 0.125f * a0 + 0.375f * a1;
    float h3 = 0.375f * a1 + 0.125f * a2;
    float h4 = 0.125f * a1 + 0.375f * a2;
    float c0, s0, c1, s1, c2, s2, c3, s3, c4, s4;
    __sincosf(h0, &s0, &c0);
    __sincosf(h1, &s1, &c1);
    __sincosf(h2, &s2, &c2);
    __sincosf(h3, &s3, &c3);
    __sincosf(h4, &s4, &c4);
    float t00 = c0 * c1, t01 = c0 * s1, t10 = s0 * c1, t11 = s0 * s1;
    pa[0] = t00 * c2; pa[1] = t00 * s2;
    pa[2] = t01 * c2; pa[3] = t01 * s2;
    pa[4] = t10 * c2; pa[5] = t10 * s2;
    pa[6] = t11 * c2; pa[7] = t11 * s2;
    pb[0] = c3 * c4; pb[1] = c3 * s4;
    pb[2] = s3 * c4; pb[3] = s3 * s4;
}

// ---------------------------------------------------------------------------
// Main kernel: 2 batch elements/thread, scalar psi, f32x2 packs TWO OUTPUT
// ROWS. M rows 0..7 from SMEM, rows 8..15 from CONSTANT (dual ports).
// Two-pass epilogue keeps live registers low; 5 CTAs/SM for latency hiding.
// ---------------------------------------------------------------------------
__global__ void __launch_bounds__(128, 5) qsrgan_main_kernel(
    const float* __restrict__ in,
    float* __restrict__ out,
    int B)
{
    __shared__ __align__(16) float sM[1024];  // 4 KB: rows 0..7
    {
        const float4* src = (const float4*)g_M;
        float4* dst = (float4*)sM;
#pragma unroll
        for (int i = threadIdx.x; i < 256; i += 128)
            dst[i] = src[i];
    }
    __syncthreads();

    long long b = ((long long)blockIdx.x * 128 + threadIdx.x) * 2;
    if (b >= B) return;
    long long i1 = (b + 1 < B) ? b + 1 : b;

    float4 q0 = __ldg((const float4*)(in + b  * 16));
    float4 q1 = __ldg((const float4*)(in + i1 * 16));

    float paA[8], pbA[4], paB[8], pbB[4];
    build_psi_scalar(q0, paA, pbA);
    build_psi_scalar(q1, paB, pbB);

#pragma unroll 1
    for (int g = 0; g < 4; ++g) {
        // acc[j2][e]: rows (2*j2, 2*j2+1) of element e
        u64 acc[8][2];
#pragma unroll
        for (int j2 = 0; j2 < 8; ++j2) { acc[j2][0] = 0ULL; acc[j2][1] = 0ULL; }

#pragma unroll 8
        for (int k = 0; k < 32; ++k) {
            float pk0 = paA[k >> 2] * pbA[k & 3];
            float pk1 = paB[k >> 2] * pbB[k & 3];
            u64 P0 = pk2(pk0, pk0);
            u64 P1 = pk2(pk1, pk1);

            const ulonglong2* colS = (const ulonglong2*)sM + (g * 32 + k) * 2;
            ulonglong2 s0 = colS[0];
            ulonglong2 s1 = colS[1];
            ulonglong2 c0 = cM[(g * 32 + k) * 2 + 0];
            ulonglong2 c1 = cM[(g * 32 + k) * 2 + 1];

            acc[0][0] = fma2(s0.x, P0, acc[0][0]);
            acc[0][1] = fma2(s0.x, P1, acc[0][1]);
            acc[1][0] = fma2(s0.y, P0, acc[1][0]);
            acc[1][1] = fma2(s0.y, P1, acc[1][1]);
            acc[2][0] = fma2(s1.x, P0, acc[2][0]);
            acc[2][1] = fma2(s1.x, P1, acc[2][1]);
            acc[3][0] = fma2(s1.y, P0, acc[3][0]);
            acc[3][1] = fma2(s1.y, P1, acc[3][1]);
            acc[4][0] = fma2(c0.x, P0, acc[4][0]);
            acc[4][1] = fma2(c0.x, P1, acc[4][1]);
            acc[5][0] = fma2(c0.y, P0, acc[5][0]);
            acc[5][1] = fma2(c0.y, P1, acc[5][1]);
            acc[6][0] = fma2(c1.x, P0, acc[6][0]);
            acc[6][1] = fma2(c1.x, P1, acc[6][1]);
            acc[7][0] = fma2(c1.y, P0, acc[7][0]);
            acc[7][1] = fma2(c1.y, P1, acc[7][1]);
        }

        // Pass 1: per-element max of squares (acc stays live; no sq arrays)
        float mx0 = 0.0f, mx1 = 0.0f;
#pragma unroll
        for (int j2 = 0; j2 < 8; ++j2) {
            float y0, y1, z0, z1;
            upk2(acc[j2][0], y0, y1);
            upk2(acc[j2][1], z0, z1);
            mx0 = fmaxf(mx0, fmaxf(y0 * y0, y1 * y1));
            mx1 = fmaxf(mx1, fmaxf(z0 * z0, z1 * z1));
        }
        float r0 = __fdividef(1.0f, mx0);
        float r1 = __fdividef(1.0f, mx1);

        // Pass 2: recompute squares from acc, scale, store
        float* o0 = out + b * 64 + g * 16;
#pragma unroll
        for (int qd = 0; qd < 4; ++qd) {
            float y0, y1, y2, y3;
            upk2(acc[2 * qd + 0][0], y0, y1);
            upk2(acc[2 * qd + 1][0], y2, y3);
            ((float4*)o0)[qd] = make_float4(y0 * y0 * r0, y1 * y1 * r0,
                                            y2 * y2 * r0, y3 * y3 * r0);
        }
        if (b + 1 < B) {
            float* o1 = out + i1 * 64 + g * 16;
#pragma unroll
            for (int qd = 0; qd < 4; ++qd) {
                float z0, z1, z2, z3;
                upk2(acc[2 * qd + 0][1], z0, z1);
                upk2(acc[2 * qd + 1][1], z2, z3);
                ((float4*)o1)[qd] = make_float4(z0 * z0 * r1, z1 * z1 * r1,
                                                z2 * z2 * r1, z3 * z3 * r1);
            }
        }
    }
}

// ---------------------------------------------------------------------------
extern "C" void kernel_launch(void* const* d_in, const int* in_sizes, int n_in,
                              void* d_out, int out_size)
{
    const float* in = (const float*)d_in[0];   // (B,1,4,4) f32
    const float* qp = (const float*)d_in[1];   // (4, 30) f32
    float* out = (float*)d_out;                // (B, 64) f32

    int B = in_sizes[0] / 16;
    int nthreads = (B + 1) / 2;
    int blocks = (nthreads + 127) / 128;

    precompute_M_kernel<<<1, 128>>>(qp);

    void* gM_ptr = nullptr;
    cudaGetSymbolAddress(&gM_ptr, g_M);
    cudaMemcpyToSymbolAsync(cM, (const char*)gM_ptr + 1024 * sizeof(float),
                            1024 * sizeof(float), 0,
                            cudaMemcpyDeviceToDevice, 0);

    qsrgan_main_kernel<<<blocks, 128>>>(in, out, B);
}

// round 15
// speedup vs baseline: 1.0401x; 1.0401x over previous
#include <cuda_runtime.h>
#include <cstddef>
#include <cstdint>

typedef unsigned long long u64;

// M matrix in DUAL-PORT split layout (2048 floats total):
//   floats [0, 1024):  SMEM half — rows 0..7  as row-pairs j2=0..3
//   floats [1024,2048): CONST half — rows 8..15 as row-pairs j2=4..7
__device__ float g_M[2048];
__constant__ ulonglong2 cM[256];   // 4 KB const half

// ---------------------------------------------------------------------------
// Precompute: simulate the weight-only circuit on all 32 basis states for
// each of the 4 generators. Thread t = g*32 + k simulates column k of U_g.
// ---------------------------------------------------------------------------
__global__ void precompute_M_kernel(const float* __restrict__ qp)
{
    int t = threadIdx.x;
    if (t >= 128) return;
    int g = t >> 5;
    int k = t & 31;

    float st[32];
#pragma unroll
    for (int i = 0; i < 32; ++i) st[i] = 0.0f;
    st[k] = 1.0f;

#pragma unroll 1
    for (int d = 0; d < 6; ++d) {
#pragma unroll
        for (int w = 0; w < 5; ++w) {
            float th = qp[g * 30 + d * 5 + w] * 0.5f;
            float s, c;
            __sincosf(th, &s, &c);
            const int stride = 16 >> w;
#pragma unroll
            for (int i = 0; i < 32; ++i) {
                if (i & stride) continue;
                float a0 = st[i];
                float a1 = st[i + stride];
                st[i]          = c * a0 - s * a1;
                st[i + stride] = s * a0 + c * a1;
            }
        }
#pragma unroll
        for (int w = 0; w < 4; ++w) {
            const int m = (16 >> w) | (8 >> w);
#pragma unroll
            for (int i = 0; i < 32; ++i)
                if ((i & m) == m) st[i] = -st[i];
        }
    }

#pragma unroll
    for (int j2 = 0; j2 < 4; ++j2) {
        g_M[((g * 32 + k) * 4 + j2) * 2 + 0] = st[2 * j2 + 0];
        g_M[((g * 32 + k) * 4 + j2) * 2 + 1] = st[2 * j2 + 1];
    }
#pragma unroll
    for (int j2 = 0; j2 < 4; ++j2) {
        g_M[1024 + ((g * 32 + k) * 4 + j2) * 2 + 0] = st[8 + 2 * j2 + 0];
        g_M[1024 + ((g * 32 + k) * 4 + j2) * 2 + 1] = st[8 + 2 * j2 + 1];
    }
}

// ---------------------------------------------------------------------------
// Packed f32x2 helpers (Blackwell sm_103a)
// ---------------------------------------------------------------------------
__device__ __forceinline__ u64 pk2(float lo, float hi) {
    u64 r;
    asm("mov.b64 %0, {%1, %2};" : "=l"(r) : "f"(lo), "f"(hi));
    return r;
}
__device__ __forceinline__ void upk2(u64 v, float& lo, float& hi) {
    asm("mov.b64 {%0, %1}, %2;" : "=f"(lo), "=f"(hi) : "l"(v));
}
__device__ __forceinline__ u64 fma2(u64 a, u64 b, u64 c) {
    u64 d;
    asm("fma.rn.f32x2 %0, %1, %2, %3;" : "=l"(d) : "l"(a), "l"(b), "l"(c));
    return d;
}

// Scalar Kronecker factors for ONE batch element.
__device__ __forceinline__ void build_psi_scalar(
    float4 q, float pa[8], float pb[4])
{
    float a0 = q.x, a1 = q.y, a2 = q.z;
    float h0 = 0.5f   * a0;
    float h1 = 0.375f * a0 + 0.125f * a1;
    float h2 = 0.125f * a0 + 0.375f * a1;
    float h3 = 0.375f * a1 + 0.125f * a2;
    float h4 = 0.125f * a1 + 0.375f * a2;
    float c0, s0, c1, s1, c2, s2, c3, s3, c4, s4;
    __sincosf(h0, &s0, &c0);
    __sincosf(h1, &s1, &c1);
    __sincosf(h2, &s2, &c2);
    __sincosf(h3, &s3, &c3);
    __sincosf(h4, &s4, &c4);
    float t00 = c0 * c1, t01 = c0 * s1, t10 = s0 * c1, t11 = s0 * s1;
    pa[0] = t00 * c2; pa[1] = t00 * s2;
    pa[2] = t01 * c2; pa[3] = t01 * s2;
    pa[4] = t10 * c2; pa[5] = t10 * s2;
    pa[6] = t11 * c2; pa[7] = t11 * s2;
    pb[0] = c3 * c4; pb[1] = c3 * s4;
    pb[2] = s3 * c4; pb[3] = s3 * s4;
}

// ---------------------------------------------------------------------------
// Main kernel: PERSISTENT grid-stride over pair-blocks. 2 batch elements per
// thread, scalar psi, f32x2 packs TWO OUTPUT ROWS. M rows 0..7 from SMEM,
// rows 8..15 from CONSTANT (dual independent ports). 6 CTAs/SM resident for
// the whole kernel — no low-occupancy tail wave.
// ---------------------------------------------------------------------------
__global__ void __launch_bounds__(128, 6) qsrgan_main_kernel(
    const float* __restrict__ in,
    float* __restrict__ out,
    int B)
{
    __shared__ __align__(16) float sM[1024];  // 4 KB: rows 0..7
    {
        const float4* src = (const float4*)g_M;
        float4* dst = (float4*)sM;
#pragma unroll
        for (int i = threadIdx.x; i < 256; i += 128)
            dst[i] = src[i];
    }
    __syncthreads();

    const int npairs = (B + 1) / 2;        // one pair of elements per thread
    const int nblk   = (npairs + 127) / 128;

#pragma unroll 1
    for (int blk = blockIdx.x; blk < nblk; blk += gridDim.x) {
        long long pair = (long long)blk * 128 + threadIdx.x;
        if (pair >= npairs) continue;
        long long b  = pair * 2;
        long long i1 = (b + 1 < B) ? b + 1 : b;

        float4 q0 = __ldg((const float4*)(in + b  * 16));
        float4 q1 = __ldg((const float4*)(in + i1 * 16));

        float paA[8], pbA[4], paB[8], pbB[4];
        build_psi_scalar(q0, paA, pbA);
        build_psi_scalar(q1, paB, pbB);

#pragma unroll 1
        for (int g = 0; g < 4; ++g) {
            // acc[j2][e]: rows (2*j2, 2*j2+1) of element e
            u64 acc[8][2];
#pragma unroll
            for (int j2 = 0; j2 < 8; ++j2) { acc[j2][0] = 0ULL; acc[j2][1] = 0ULL; }

#pragma unroll 8
            for (int k = 0; k < 32; ++k) {
                float pk0 = paA[k >> 2] * pbA[k & 3];
                float pk1 = paB[k >> 2] * pbB[k & 3];
                u64 P0 = pk2(pk0, pk0);
                u64 P1 = pk2(pk1, pk1);

                const ulonglong2* colS = (const ulonglong2*)sM + (g * 32 + k) * 2;
                ulonglong2 s0 = colS[0];
                ulonglong2 s1 = colS[1];
                ulonglong2 c0 = cM[(g * 32 + k) * 2 + 0];
                ulonglong2 c1 = cM[(g * 32 + k) * 2 + 1];

                acc[0][0] = fma2(s0.x, P0, acc[0][0]);
                acc[0][1] = fma2(s0.x, P1, acc[0][1]);
                acc[1][0] = fma2(s0.y, P0, acc[1][0]);
                acc[1][1] = fma2(s0.y, P1, acc[1][1]);
                acc[2][0] = fma2(s1.x, P0, acc[2][0]);
                acc[2][1] = fma2(s1.x, P1, acc[2][1]);
                acc[3][0] = fma2(s1.y, P0, acc[3][0]);
                acc[3][1] = fma2(s1.y, P1, acc[3][1]);
                acc[4][0] = fma2(c0.x, P0, acc[4][0]);
                acc[4][1] = fma2(c0.x, P1, acc[4][1]);
                acc[5][0] = fma2(c0.y, P0, acc[5][0]);
                acc[5][1] = fma2(c0.y, P1, acc[5][1]);
                acc[6][0] = fma2(c1.x, P0, acc[6][0]);
                acc[6][1] = fma2(c1.x, P1, acc[6][1]);
                acc[7][0] = fma2(c1.y, P0, acc[7][0]);
                acc[7][1] = fma2(c1.y, P1, acc[7][1]);
            }

            // Pass 1: per-element max of squares
            float mx0 = 0.0f, mx1 = 0.0f;
#pragma unroll
            for (int j2 = 0; j2 < 8; ++j2) {
                float y0, y1, z0, z1;
                upk2(acc[j2][0], y0, y1);
                upk2(acc[j2][1], z0, z1);
                mx0 = fmaxf(mx0, fmaxf(y0 * y0, y1 * y1));
                mx1 = fmaxf(mx1, fmaxf(z0 * z0, z1 * z1));
            }
            float r0 = __fdividef(1.0f, mx0);
            float r1 = __fdividef(1.0f, mx1);

            // Pass 2: recompute squares from acc, scale, store
            float* o0 = out + b * 64 + g * 16;
#pragma unroll
            for (int qd = 0; qd < 4; ++qd) {
                float y0, y1, y2, y3;
                upk2(acc[2 * qd + 0][0], y0, y1);
                upk2(acc[2 * qd + 1][0], y2, y3);
                ((float4*)o0)[qd] = make_float4(y0 * y0 * r0, y1 * y1 * r0,
                                                y2 * y2 * r0, y3 * y3 * r0);
            }
            if (b + 1 < B) {
                float* o1 = out + i1 * 64 + g * 16;
#pragma unroll
                for (int qd = 0; qd < 4; ++qd) {
                    float z0, z1, z2, z3;
                    upk2(acc[2 * qd + 0][1], z0, z1);
                    upk2(acc[2 * qd + 1][1], z2, z3);
                    ((float4*)o1)[qd] = make_float4(z0 * z0 * r1, z1 * z1 * r1,
                                                    z2 * z2 * r1, z3 * z3 * r1);
                }
            }
        }
    }
}

// ---------------------------------------------------------------------------
extern "C" void kernel_launch(void* const* d_in, const int* in_sizes, int n_in,
                              void* d_out, int out_size)
{
    const float* in = (const float*)d_in[0];   // (B,1,4,4) f32
    const float* qp = (const float*)d_in[1];   // (4, 30) f32
    float* out = (float*)d_out;                // (B, 64) f32

    int B = in_sizes[0] / 16;
    int npairs = (B + 1) / 2;
    int nblk = (npairs + 127) / 128;

    int blocks = 6 * 148;                      // persistent: 6 CTAs per SM
    if (blocks > nblk) blocks = nblk;

    precompute_M_kernel<<<1, 128>>>(qp);

    void* gM_ptr = nullptr;
    cudaGetSymbolAddress(&gM_ptr, g_M);
    cudaMemcpyToSymbolAsync(cM, (const char*)gM_ptr + 1024 * sizeof(float),
                            1024 * sizeof(float), 0,
                            cudaMemcpyDeviceToDevice, 0);

    qsrgan_main_kernel<<<blocks, 128>>>(in, out, B);
}

// round 16
// speedup vs baseline: 1.1221x; 1.0788x over previous
#include <cuda_runtime.h>
#include <cstddef>
#include <cstdint>

typedef unsigned long long u64;

// M matrix in DUAL-PORT split layout (2048 floats total):
//   floats [0, 1024):  SMEM half — rows 0..7  as row-pairs j2=0..3
//   floats [1024,2048): CONST half — rows 8..15 as row-pairs j2=4..7
__device__ float g_M[2048];
__constant__ ulonglong2 cM[256];   // 4 KB const half

// ---------------------------------------------------------------------------
// Precompute: simulate the weight-only circuit on all 32 basis states for
// each of the 4 generators. Thread t = g*32 + k simulates column k of U_g.
// ---------------------------------------------------------------------------
__global__ void precompute_M_kernel(const float* __restrict__ qp)
{
    int t = threadIdx.x;
    if (t >= 128) return;
    int g = t >> 5;
    int k = t & 31;

    float st[32];
#pragma unroll
    for (int i = 0; i < 32; ++i) st[i] = 0.0f;
    st[k] = 1.0f;

#pragma unroll 1
    for (int d = 0; d < 6; ++d) {
#pragma unroll
        for (int w = 0; w < 5; ++w) {
            float th = qp[g * 30 + d * 5 + w] * 0.5f;
            float s, c;
            __sincosf(th, &s, &c);
            const int stride = 16 >> w;
#pragma unroll
            for (int i = 0; i < 32; ++i) {
                if (i & stride) continue;
                float a0 = st[i];
                float a1 = st[i + stride];
                st[i]          = c * a0 - s * a1;
                st[i + stride] = s * a0 + c * a1;
            }
        }
#pragma unroll
        for (int w = 0; w < 4; ++w) {
            const int m = (16 >> w) | (8 >> w);
#pragma unroll
            for (int i = 0; i < 32; ++i)
                if ((i & m) == m) st[i] = -st[i];
        }
    }

#pragma unroll
    for (int j2 = 0; j2 < 4; ++j2) {
        g_M[((g * 32 + k) * 4 + j2) * 2 + 0] = st[2 * j2 + 0];
        g_M[((g * 32 + k) * 4 + j2) * 2 + 1] = st[2 * j2 + 1];
    }
#pragma unroll
    for (int j2 = 0; j2 < 4; ++j2) {
        g_M[1024 + ((g * 32 + k) * 4 + j2) * 2 + 0] = st[8 + 2 * j2 + 0];
        g_M[1024 + ((g * 32 + k) * 4 + j2) * 2 + 1] = st[8 + 2 * j2 + 1];
    }
}

// ---------------------------------------------------------------------------
// Packed f32x2 helpers (Blackwell sm_103a)
// ---------------------------------------------------------------------------
__device__ __forceinline__ u64 pk2(float lo, float hi) {
    u64 r;
    asm("mov.b64 %0, {%1, %2};" : "=l"(r) : "f"(lo), "f"(hi));
    return r;
}
__device__ __forceinline__ void upk2(u64 v, float& lo, float& hi) {
    asm("mov.b64 {%0, %1}, %2;" : "=f"(lo), "=f"(hi) : "l"(v));
}
__device__ __forceinline__ u64 fma2(u64 a, u64 b, u64 c) {
    u64 d;
    asm("fma.rn.f32x2 %0, %1, %2, %3;" : "=l"(d) : "l"(a), "l"(b), "l"(c));
    return d;
}

// Scalar Kronecker factors for ONE batch element.
__device__ __forceinline__ void build_psi_scalar(
    float4 q, float pa[8], float pb[4])
{
    float a0 = q.x, a1 = q.y, a2 = q.z;
    float h0 = 0.5f   * a0;
    float h1 = 0.375f * a0 + 0.125f * a1;
    float h2 = 0.125f * a0 + 0.375f * a1;
    float h3 = 0.375f * a1 + 0.125f * a2;
    float h4 = 0.125f * a1 + 0.375f * a2;
    float c0, s0, c1, s1, c2, s2, c3, s3, c4, s4;
    __sincosf(h0, &s0, &c0);
    __sincosf(h1, &s1, &c1);
    __sincosf(h2, &s2, &c2);
    __sincosf(h3, &s3, &c3);
    __sincosf(h4, &s4, &c4);
    float t00 = c0 * c1, t01 = c0 * s1, t10 = s0 * c1, t11 = s0 * s1;
    pa[0] = t00 * c2; pa[1] = t00 * s2;
    pa[2] = t01 * c2; pa[3] = t01 * s2;
    pa[4] = t10 * c2; pa[5] = t10 * s2;
    pa[6] = t11 * c2; pa[7] = t11 * s2;
    pb[0] = c3 * c4; pb[1] = c3 * s4;
    pb[2] = s3 * c4; pb[3] = s3 * s4;
}

// ---------------------------------------------------------------------------
// Main kernel: block of 128 threads handles 256 elements (thread t owns
// elements base+t and base+t+128). Dual-port M (smem rows 0..7, const rows
// 8..15). Per-g results go through a stride-5 smem staging buffer so global
// stores are warp-coalesced (8 lines/STG vs 32 for direct per-thread stores).
// ---------------------------------------------------------------------------
__global__ void __launch_bounds__(128, 4) qsrgan_main_kernel(
    const float* __restrict__ in,
    float* __restrict__ out,
    int B)
{
    __shared__ __align__(16) float sM[1024];      // 4 KB: M rows 0..7
    __shared__ __align__(16) float4 stage[256 * 5]; // 20 KB staging (stride-5)

    {
        const float4* src = (const float4*)g_M;
        float4* dst = (float4*)sM;
#pragma unroll
        for (int i = threadIdx.x; i < 256; i += 128)
            dst[i] = src[i];
    }
    __syncthreads();

    const int tid = threadIdx.x;
    const long long base = (long long)blockIdx.x * 256;

    long long eLo = base + tid;
    long long eHi = base + tid + 128;
    long long eLoC = (eLo < B) ? eLo : (B - 1);
    long long eHiC = (eHi < B) ? eHi : (B - 1);

    float4 q0 = __ldg((const float4*)(in + eLoC * 16));
    float4 q1 = __ldg((const float4*)(in + eHiC * 16));

    float paA[8], pbA[4], paB[8], pbB[4];
    build_psi_scalar(q0, paA, pbA);
    build_psi_scalar(q1, paB, pbB);

#pragma unroll 1
    for (int g = 0; g < 4; ++g) {
        // acc[j2][e]: rows (2*j2, 2*j2+1); e=0 -> eLo, e=1 -> eHi
        u64 acc[8][2];
#pragma unroll
        for (int j2 = 0; j2 < 8; ++j2) { acc[j2][0] = 0ULL; acc[j2][1] = 0ULL; }

#pragma unroll 8
        for (int k = 0; k < 32; ++k) {
            float pk0 = paA[k >> 2] * pbA[k & 3];
            float pk1 = paB[k >> 2] * pbB[k & 3];
            u64 P0 = pk2(pk0, pk0);
            u64 P1 = pk2(pk1, pk1);

            const ulonglong2* colS = (const ulonglong2*)sM + (g * 32 + k) * 2;
            ulonglong2 s0 = colS[0];
            ulonglong2 s1 = colS[1];
            ulonglong2 c0 = cM[(g * 32 + k) * 2 + 0];
            ulonglong2 c1 = cM[(g * 32 + k) * 2 + 1];

            acc[0][0] = fma2(s0.x, P0, acc[0][0]);
            acc[0][1] = fma2(s0.x, P1, acc[0][1]);
            acc[1][0] = fma2(s0.y, P0, acc[1][0]);
            acc[1][1] = fma2(s0.y, P1, acc[1][1]);
            acc[2][0] = fma2(s1.x, P0, acc[2][0]);
            acc[2][1] = fma2(s1.x, P1, acc[2][1]);
            acc[3][0] = fma2(s1.y, P0, acc[3][0]);
            acc[3][1] = fma2(s1.y, P1, acc[3][1]);
            acc[4][0] = fma2(c0.x, P0, acc[4][0]);
            acc[4][1] = fma2(c0.x, P1, acc[4][1]);
            acc[5][0] = fma2(c0.y, P0, acc[5][0]);
            acc[5][1] = fma2(c0.y, P1, acc[5][1]);
            acc[6][0] = fma2(c1.x, P0, acc[6][0]);
            acc[6][1] = fma2(c1.x, P1, acc[6][1]);
            acc[7][0] = fma2(c1.y, P0, acc[7][0]);
            acc[7][1] = fma2(c1.y, P1, acc[7][1]);
        }

        // Pass 1: per-element max of squares
        float mx0 = 0.0f, mx1 = 0.0f;
#pragma unroll
        for (int j2 = 0; j2 < 8; ++j2) {
            float y0, y1, z0, z1;
            upk2(acc[j2][0], y0, y1);
            upk2(acc[j2][1], z0, z1);
            mx0 = fmaxf(mx0, fmaxf(y0 * y0, y1 * y1));
            mx1 = fmaxf(mx1, fmaxf(z0 * z0, z1 * z1));
        }
        float r0 = __fdividef(1.0f, mx0);
        float r1 = __fdividef(1.0f, mx1);

        // Stage results (stride-5 quads per element: conflict-free STS)
#pragma unroll
        for (int qd = 0; qd < 4; ++qd) {
            float y0, y1, y2, y3;
            upk2(acc[2 * qd + 0][0], y0, y1);
            upk2(acc[2 * qd + 1][0], y2, y3);
            stage[tid * 5 + qd] = make_float4(y0 * y0 * r0, y1 * y1 * r0,
                                              y2 * y2 * r0, y3 * y3 * r0);
            float z0, z1, z2, z3;
            upk2(acc[2 * qd + 0][1], z0, z1);
            upk2(acc[2 * qd + 1][1], z2, z3);
            stage[(tid + 128) * 5 + qd] = make_float4(z0 * z0 * r1, z1 * z1 * r1,
                                                      z2 * z2 * r1, z3 * z3 * r1);
        }
        __syncthreads();

        // Cooperative coalesced store: 1024 float4s (256 elems x 4 quads)
#pragma unroll
        for (int i = 0; i < 8; ++i) {
            int q = i * 128 + tid;
            int e = q >> 2;
            int jq = q & 3;
            long long ge = base + e;
            if (ge < B) {
                float4 v = stage[e * 5 + jq];
                *(float4*)(out + ge * 64 + g * 16 + jq * 4) = v;
            }
        }
        __syncthreads();
    }
}

// ---------------------------------------------------------------------------
extern "C" void kernel_launch(void* const* d_in, const int* in_sizes, int n_in,
                              void* d_out, int out_size)
{
    const float* in = (const float*)d_in[0];   // (B,1,4,4) f32
    const float* qp = (const float*)d_in[1];   // (4, 30) f32
    float* out = (float*)d_out;                // (B, 64) f32

    int B = in_sizes[0] / 16;
    int blocks = (B + 255) / 256;

    precompute_M_kernel<<<1, 128>>>(qp);

    void* gM_ptr = nullptr;
    cudaGetSymbolAddress(&gM_ptr, g_M);
    cudaMemcpyToSymbolAsync(cM, (const char*)gM_ptr + 1024 * sizeof(float),
                            1024 * sizeof(float), 0,
                            cudaMemcpyDeviceToDevice, 0);

    qsrgan_main_kernel<<<blocks, 128>>>(in, out, B);
}

// round 17
// speedup vs baseline: 1.2843x; 1.1446x over previous
#include <cuda_runtime.h>
#include <cstddef>
#include <cstdint>

typedef unsigned long long u64;

// M matrix in DUAL-PORT split layout (2048 floats total), rebalanced:
//   floats [0, 512):   SMEM half  — row-pairs j2=0,1 (rows 0..3)
//       g_M[((g*32+k)*2 + j2)*2 + c]
//   floats [512,2048): CONST half — row-pairs j2=2..7 (rows 4..15)
//       g_M[512 + ((g*32+k)*6 + (j2-2))*2 + c]
// Per k the mainloop issues 1x LDS.128 + 3x LDC.128 — balancing the smem
// crossbar (4 cyc/SM per uniform 16B load) against the constant port
// (8 cyc/SMSP = ~2 cyc/SM-equivalent per load).
__device__ float g_M[2048];
__constant__ ulonglong2 cM[384];   // 6 KB const half (j2=2..7)

// ---------------------------------------------------------------------------
// Precompute: simulate the weight-only circuit on all 32 basis states for
// each of the 4 generators. Thread t = g*32 + k simulates column k of U_g.
// ---------------------------------------------------------------------------
__global__ void precompute_M_kernel(const float* __restrict__ qp)
{
    int t = threadIdx.x;
    if (t >= 128) return;
    int g = t >> 5;
    int k = t & 31;

    float st[32];
#pragma unroll
    for (int i = 0; i < 32; ++i) st[i] = 0.0f;
    st[k] = 1.0f;

#pragma unroll 1
    for (int d = 0; d < 6; ++d) {
#pragma unroll
        for (int w = 0; w < 5; ++w) {
            float th = qp[g * 30 + d * 5 + w] * 0.5f;
            float s, c;
            __sincosf(th, &s, &c);
            const int stride = 16 >> w;
#pragma unroll
            for (int i = 0; i < 32; ++i) {
                if (i & stride) continue;
                float a0 = st[i];
                float a1 = st[i + stride];
                st[i]          = c * a0 - s * a1;
                st[i + stride] = s * a0 + c * a1;
            }
        }
#pragma unroll
        for (int w = 0; w < 4; ++w) {
            const int m = (16 >> w) | (8 >> w);
#pragma unroll
            for (int i = 0; i < 32; ++i)
                if ((i & m) == m) st[i] = -st[i];
        }
    }

    // SMEM half: row-pairs j2 = 0,1 (rows 0..3)
#pragma unroll
    for (int j2 = 0; j2 < 2; ++j2) {
        g_M[((g * 32 + k) * 2 + j2) * 2 + 0] = st[2 * j2 + 0];
        g_M[((g * 32 + k) * 2 + j2) * 2 + 1] = st[2 * j2 + 1];
    }
    // CONST half: row-pairs j2 = 2..7 (rows 4..15)
#pragma unroll
    for (int j2 = 2; j2 < 8; ++j2) {
        g_M[512 + ((g * 32 + k) * 6 + (j2 - 2)) * 2 + 0] = st[2 * j2 + 0];
        g_M[512 + ((g * 32 + k) * 6 + (j2 - 2)) * 2 + 1] = st[2 * j2 + 1];
    }
}

// ---------------------------------------------------------------------------
// Packed f32x2 helpers (Blackwell sm_103a)
// ---------------------------------------------------------------------------
__device__ __forceinline__ u64 pk2(float lo, float hi) {
    u64 r;
    asm("mov.b64 %0, {%1, %2};" : "=l"(r) : "f"(lo), "f"(hi));
    return r;
}
__device__ __forceinline__ void upk2(u64 v, float& lo, float& hi) {
    asm("mov.b64 {%0, %1}, %2;" : "=f"(lo), "=f"(hi) : "l"(v));
}
__device__ __forceinline__ u64 fma2(u64 a, u64 b, u64 c) {
    u64 d;
    asm("fma.rn.f32x2 %0, %1, %2, %3;" : "=l"(d) : "l"(a), "l"(b), "l"(c));
    return d;
}

// Scalar Kronecker factors for ONE batch element.
__device__ __forceinline__ void build_psi_scalar(
    float4 q, float pa[8], float pb[4])
{
    float a0 = q.x, a1 = q.y, a2 = q.z;
    float h0 = 0.5f   * a0;
    float h1 = 0.375f * a0 + 0.125f * a1;
    float h2 = 0.125f * a0 + 0.375f * a1;
    float h3 = 0.375f * a1 + 0.125f * a2;
    float h4 = 0.125f * a1 + 0.375f * a2;
    float c0, s0, c1, s1, c2, s2, c3, s3, c4, s4;
    __sincosf(h0, &s0, &c0);
    __sincosf(h1, &s1, &c1);
    __sincosf(h2, &s2, &c2);
    __sincosf(h3, &s3, &c3);
    __sincosf(h4, &s4, &c4);
    float t00 = c0 * c1, t01 = c0 * s1, t10 = s0 * c1, t11 = s0 * s1;
    pa[0] = t00 * c2; pa[1] = t00 * s2;
    pa[2] = t01 * c2; pa[3] = t01 * s2;
    pa[4] = t10 * c2; pa[5] = t10 * s2;
    pa[6] = t11 * c2; pa[7] = t11 * s2;
    pb[0] = c3 * c4; pb[1] = c3 * s4;
    pb[2] = s3 * c4; pb[3] = s3 * s4;
}

// ---------------------------------------------------------------------------
// Main kernel: block of 128 threads handles 256 elements (thread t owns
// elements base+t and base+t+128). Rebalanced dual-port M (smem rows 0..3,
// const rows 4..15). Stride-5 smem staging -> coalesced global stores.
// ---------------------------------------------------------------------------
__global__ void __launch_bounds__(128, 4) qsrgan_main_kernel(
    const float* __restrict__ in,
    float* __restrict__ out,
    int B)
{
    __shared__ __align__(16) float sM[512];          // 2 KB: M rows 0..3
    __shared__ __align__(16) float4 stage[256 * 5];  // 20 KB staging (stride-5)

    {
        const float4* src = (const float4*)g_M;
        float4* dst = (float4*)sM;
#pragma unroll
        for (int i = threadIdx.x; i < 128; i += 128)
            dst[i] = src[i];
    }
    __syncthreads();

    const int tid = threadIdx.x;
    const long long base = (long long)blockIdx.x * 256;

    long long eLo = base + tid;
    long long eHi = base + tid + 128;
    long long eLoC = (eLo < B) ? eLo : (B - 1);
    long long eHiC = (eHi < B) ? eHi : (B - 1);

    float4 q0 = __ldg((const float4*)(in + eLoC * 16));
    float4 q1 = __ldg((const float4*)(in + eHiC * 16));

    float paA[8], pbA[4], paB[8], pbB[4];
    build_psi_scalar(q0, paA, pbA);
    build_psi_scalar(q1, paB, pbB);

#pragma unroll 1
    for (int g = 0; g < 4; ++g) {
        // acc[j2][e]: rows (2*j2, 2*j2+1); e=0 -> eLo, e=1 -> eHi
        u64 acc[8][2];
#pragma unroll
        for (int j2 = 0; j2 < 8; ++j2) { acc[j2][0] = 0ULL; acc[j2][1] = 0ULL; }

#pragma unroll 8
        for (int k = 0; k < 32; ++k) {
            float pk0 = paA[k >> 2] * pbA[k & 3];
            float pk1 = paB[k >> 2] * pbB[k & 3];
            u64 P0 = pk2(pk0, pk0);
            u64 P1 = pk2(pk1, pk1);

            // rows 0..3 from SMEM (1x LDS.128)
            ulonglong2 s0 = ((const ulonglong2*)sM)[g * 32 + k];
            // rows 4..15 from CONSTANT (3x LDC.128)
            ulonglong2 c0 = cM[(g * 32 + k) * 3 + 0];
            ulonglong2 c1 = cM[(g * 32 + k) * 3 + 1];
            ulonglong2 c2 = cM[(g * 32 + k) * 3 + 2];

            acc[0][0] = fma2(s0.x, P0, acc[0][0]);
            acc[0][1] = fma2(s0.x, P1, acc[0][1]);
            acc[1][0] = fma2(s0.y, P0, acc[1][0]);
            acc[1][1] = fma2(s0.y, P1, acc[1][1]);
            acc[2][0] = fma2(c0.x, P0, acc[2][0]);
            acc[2][1] = fma2(c0.x, P1, acc[2][1]);
            acc[3][0] = fma2(c0.y, P0, acc[3][0]);
            acc[3][1] = fma2(c0.y, P1, acc[3][1]);
            acc[4][0] = fma2(c1.x, P0, acc[4][0]);
            acc[4][1] = fma2(c1.x, P1, acc[4][1]);
            acc[5][0] = fma2(c1.y, P0, acc[5][0]);
            acc[5][1] = fma2(c1.y, P1, acc[5][1]);
            acc[6][0] = fma2(c2.x, P0, acc[6][0]);
            acc[6][1] = fma2(c2.x, P1, acc[6][1]);
            acc[7][0] = fma2(c2.y, P0, acc[7][0]);
            acc[7][1] = fma2(c2.y, P1, acc[7][1]);
        }

        // Pass 1: per-element max of squares
        float mx0 = 0.0f, mx1 = 0.0f;
#pragma unroll
        for (int j2 = 0; j2 < 8; ++j2) {
            float y0, y1, z0, z1;
            upk2(acc[j2][0], y0, y1);
            upk2(acc[j2][1], z0, z1);
            mx0 = fmaxf(mx0, fmaxf(y0 * y0, y1 * y1));
            mx1 = fmaxf(mx1, fmaxf(z0 * z0, z1 * z1));
        }
        float r0 = __fdividef(1.0f, mx0);
        float r1 = __fdividef(1.0f, mx1);

        // Stage results (stride-5 quads per element: conflict-free STS)
#pragma unroll
        for (int qd = 0; qd < 4; ++qd) {
            float y0, y1, y2, y3;
            upk2(acc[2 * qd + 0][0], y0, y1);
            upk2(acc[2 * qd + 1][0], y2, y3);
            stage[tid * 5 + qd] = make_float4(y0 * y0 * r0, y1 * y1 * r0,
                                              y2 * y2 * r0, y3 * y3 * r0);
            float z0, z1, z2, z3;
            upk2(acc[2 * qd + 0][1], z0, z1);
            upk2(acc[2 * qd + 1][1], z2, z3);
            stage[(tid + 128) * 5 + qd] = make_float4(z0 * z0 * r1, z1 * z1 * r1,
                                                      z2 * z2 * r1, z3 * z3 * r1);
        }
        __syncthreads();

        // Cooperative coalesced store: 1024 float4s (256 elems x 4 quads)
#pragma unroll
        for (int i = 0; i < 8; ++i) {
            int q = i * 128 + tid;
            int e = q >> 2;
            int jq = q & 3;
            long long ge = base + e;
            if (ge < B) {
                float4 v = stage[e * 5 + jq];
                *(float4*)(out + ge * 64 + g * 16 + jq * 4) = v;
            }
        }
        __syncthreads();
    }
}

// ---------------------------------------------------------------------------
extern "C" void kernel_launch(void* const* d_in, const int* in_sizes, int n_in,
                              void* d_out, int out_size)
{
    const float* in = (const float*)d_in[0];   // (B,1,4,4) f32
    const float* qp = (const float*)d_in[1];   // (4, 30) f32
    float* out = (float*)d_out;                // (B, 64) f32

    int B = in_sizes[0] / 16;
    int blocks = (B + 255) / 256;

    precompute_M_kernel<<<1, 128>>>(qp);

    void* gM_ptr = nullptr;
    cudaGetSymbolAddress(&gM_ptr, g_M);
    cudaMemcpyToSymbolAsync(cM, (const char*)gM_ptr + 512 * sizeof(float),
                            1536 * sizeof(float), 0,
                            cudaMemcpyDeviceToDevice, 0);

    qsrgan_main_kernel<<<blocks, 128>>>(in, out, B);
}